// round 14
// baseline (speedup 1.0000x reference)
#include <cuda_runtime.h>
#include <cuda_bf16.h>
#include <math.h>
#include <stdint.h>

// Problem constants
#define T_TOK 4096   // B*S tokens
#define D_DIM 1024   // embed dim
#define U_DIM 4096   // ffn dim
#define E_NUM 8      // experts

// ---------------- scratch (static device globals; no allocation) -----------
__device__ __nv_bfloat16 g_xh [(size_t)T_TOK * D_DIM];
__device__ __nv_bfloat16 g_xl [(size_t)T_TOK * D_DIM];
__device__ __nv_bfloat16 g_wuh[(size_t)E_NUM * U_DIM * D_DIM];
__device__ __nv_bfloat16 g_wul[(size_t)E_NUM * U_DIM * D_DIM];
__device__ __nv_bfloat16 g_wdh[(size_t)E_NUM * D_DIM * U_DIM];
__device__ __nv_bfloat16 g_wdl[(size_t)E_NUM * D_DIM * U_DIM];
__device__ __nv_bfloat16 g_Hh [(size_t)T_TOK * 2 * U_DIM];
__device__ __nv_bfloat16 g_Hl [(size_t)T_TOK * 2 * U_DIM];
__device__ int   g_tok[E_NUM * T_TOK];
__device__ float g_wt [E_NUM * T_TOK];
__device__ int   g_cnt[E_NUM];
__device__ int   g_off[E_NUM];

// ---------------- PTX helpers (baseline sm_80+ ISA only) -------------------
__device__ __forceinline__ uint32_t smem_u32(const void* p) {
    uint32_t a;
    asm("{ .reg .u64 t; cvta.to.shared.u64 t, %1; cvt.u32.u64 %0, t; }" : "=r"(a) : "l"(p));
    return a;
}

#define CP16(dst, src)  asm volatile("cp.async.cg.shared.global [%0], [%1], 16;" :: "r"(dst), "l"(src))
#define CP_COMMIT()     asm volatile("cp.async.commit_group;" ::: "memory")
#define CP_WAIT1()      asm volatile("cp.async.wait_group 1;" ::: "memory")
#define CP_WAIT0()      asm volatile("cp.async.wait_group 0;" ::: "memory")

#define LDSM4(r0, r1, r2, r3, addr) \
    asm volatile("ldmatrix.sync.aligned.m8n8.x4.shared.b16 {%0,%1,%2,%3}, [%4];" \
                 : "=r"(r0), "=r"(r1), "=r"(r2), "=r"(r3) : "r"(addr))

__device__ __forceinline__ void mma16816(float* d, const uint32_t* a, const uint32_t* b) {
    asm volatile(
        "mma.sync.aligned.m16n8k16.row.col.f32.bf16.bf16.f32 "
        "{%0,%1,%2,%3}, {%4,%5,%6,%7}, {%8,%9}, {%0,%1,%2,%3};"
        : "+f"(d[0]), "+f"(d[1]), "+f"(d[2]), "+f"(d[3])
        : "r"(a[0]), "r"(a[1]), "r"(a[2]), "r"(a[3]), "r"(b[0]), "r"(b[1]));
}

// SMEM tile: 128 rows x 4 chunks of 16B (BK=32 bf16). XOR swizzle keeps
// ldmatrix 8-row reads on distinct banks: chunk' = chunk ^ ((row>>1)&3).
__device__ __forceinline__ uint32_t tile_off(int row, int chunk) {
    return (uint32_t)(row * 64 + ((chunk ^ ((row >> 1) & 3)) << 4));
}

__device__ __forceinline__ float gelu_exact(float v) {
    return 0.5f * v * (1.f + erff(v * 0.70710678118654752f));
}
__device__ __forceinline__ void split_bf16(float v, __nv_bfloat16& h, __nv_bfloat16& l) {
    h = __float2bfloat16_rn(v);
    l = __float2bfloat16_rn(v - __bfloat162float(h));
}

// ---------------- input split: fp32 -> bf16 hi + bf16 lo -------------------
__global__ void split_kernel(const float* __restrict__ src,
                             __nv_bfloat16* __restrict__ hi,
                             __nv_bfloat16* __restrict__ lo, int n) {
    int stride = gridDim.x * blockDim.x * 4;
    for (int i = (blockIdx.x * blockDim.x + threadIdx.x) * 4; i < n; i += stride) {
        float4 v = *(const float4*)(src + i);
        __nv_bfloat16 h0, h1, h2, h3, l0, l1, l2, l3;
        split_bf16(v.x, h0, l0); split_bf16(v.y, h1, l1);
        split_bf16(v.z, h2, l2); split_bf16(v.w, h3, l3);
        *(__nv_bfloat162*)(hi + i)     = __halves2bfloat162(h0, h1);
        *(__nv_bfloat162*)(hi + i + 2) = __halves2bfloat162(h2, h3);
        *(__nv_bfloat162*)(lo + i)     = __halves2bfloat162(l0, l1);
        *(__nv_bfloat162*)(lo + i + 2) = __halves2bfloat162(l2, l3);
    }
}

// ---------------- router ----------------------------------------------------
__global__ void zero_cnt_kernel() {
    if (threadIdx.x < E_NUM) g_cnt[threadIdx.x] = 0;
}

__global__ void router_kernel(const float* __restrict__ x,
                              const float* __restrict__ wr) {
    int t    = blockIdx.x * 4 + (threadIdx.x >> 5);
    int lane = threadIdx.x & 31;
    if (t >= T_TOK) return;
    const float* xr = x + (size_t)t * D_DIM;

    float logit[E_NUM];
#pragma unroll
    for (int e = 0; e < E_NUM; e++) {
        const float* w = wr + e * D_DIM;
        float s = 0.f;
        for (int i = lane; i < D_DIM; i += 32)
            s += xr[i] * w[i];
#pragma unroll
        for (int o = 16; o > 0; o >>= 1)
            s += __shfl_xor_sync(0xffffffffu, s, o);
        logit[e] = s;
    }

    if (lane == 0) {
        int e0 = 0; float l0 = logit[0];
#pragma unroll
        for (int e = 1; e < E_NUM; e++)
            if (logit[e] > l0) { l0 = logit[e]; e0 = e; }
        int e1 = -1; float l1 = -INFINITY;
#pragma unroll
        for (int e = 0; e < E_NUM; e++)
            if (e != e0 && logit[e] > l1) { l1 = logit[e]; e1 = e; }

        float p1 = expf(l1 - l0);
        float inv = 1.f / (1.f + p1);
        float w0 = inv, w1 = p1 * inv;

        int p;
        p = atomicAdd(&g_cnt[e0], 1);
        g_tok[e0 * T_TOK + p] = t;  g_wt[e0 * T_TOK + p] = w0;
        p = atomicAdd(&g_cnt[e1], 1);
        g_tok[e1 * T_TOK + p] = t;  g_wt[e1 * T_TOK + p] = w1;
    }
}

__global__ void offsets_kernel() {
    if (threadIdx.x == 0) {
        int acc = 0;
#pragma unroll
        for (int e = 0; e < E_NUM; e++) { g_off[e] = acc; acc += g_cnt[e]; }
    }
}

// ---------------- grouped GEMM: mma.sync bf16, 3-pass hi/lo split ----------
// C[m,n] = sum_k A[m,k]*B[n,k], A gathered (up: tokens, down: H rows).
// Tile BM=128, BN=128, BK=32; 8 warps each compute 32(M) x 64(N).
// SMEM layout: [s_tok 512B][s_wt 512B][stage0: Ah 8K|Al 8K|Bh 8K|Bl 8K][stage1 ...]

static constexpr int SMEM_TILES = 1024;
static constexpr int STAGE_BYTES = 32768;
static constexpr int SMEM_BYTES = SMEM_TILES + 2 * STAGE_BYTES;  // 66560

template<int KDIM, bool IS_UP>
__global__ void __launch_bounds__(256, 2)
moe_mma(const __nv_bfloat16* __restrict__ Ah, const __nv_bfloat16* __restrict__ Al,
        const __nv_bfloat16* __restrict__ Wh, const __nv_bfloat16* __restrict__ Wl,
        const float* __restrict__ bias, float* __restrict__ out)
{
    constexpr int NTOT = IS_UP ? U_DIM : D_DIM;
    constexpr int NT   = KDIM / 32;

    int e   = blockIdx.z;
    int n_e = g_cnt[e];
    int m0  = blockIdx.y * 128;
    if (m0 >= n_e) return;
    int n0  = blockIdx.x * 128;
    int off = g_off[e];

    int tid  = threadIdx.x;
    int lane = tid & 31;
    int wid  = tid >> 5;
    int wm   = (wid & 3) * 32;   // warp M offset (0..96)
    int wn   = (wid >> 2) * 64;  // warp N offset (0 or 64)

    extern __shared__ __align__(16) char smem[];
    uint32_t sb = smem_u32(smem);
    int*   s_tok = (int*)(smem);
    float* s_wt  = (float*)(smem + 512);

    if (tid < 128) {
        int grow = m0 + tid;
        int idx  = e * T_TOK + (grow < n_e ? grow : n_e - 1);
        s_tok[tid] = g_tok[idx];
        s_wt[tid]  = g_wt[idx];
    }
    __syncthreads();

    // ---- per-thread cp.async slots: 2 (row,chunk) pairs, reused for 4 tiles
    int c    = tid & 3;            // 16B chunk within 64B row
    int row0 = tid >> 2;           // 0..63
    int row1 = row0 + 64;          // 64..127
    uint32_t dst0 = tile_off(row0, c);
    uint32_t dst1 = tile_off(row1, c);

    const __nv_bfloat16 *aH0, *aH1, *aL0, *aL1;
    if (IS_UP) {
        aH0 = Ah + (size_t)s_tok[row0] * KDIM + c * 8;
        aH1 = Ah + (size_t)s_tok[row1] * KDIM + c * 8;
        aL0 = Al + (size_t)s_tok[row0] * KDIM + c * 8;
        aL1 = Al + (size_t)s_tok[row1] * KDIM + c * 8;
    } else {
        int r0c = m0 + row0; if (r0c >= n_e) r0c = n_e - 1;
        int r1c = m0 + row1; if (r1c >= n_e) r1c = n_e - 1;
        aH0 = Ah + (size_t)(off + r0c) * KDIM + c * 8;
        aH1 = Ah + (size_t)(off + r1c) * KDIM + c * 8;
        aL0 = Al + (size_t)(off + r0c) * KDIM + c * 8;
        aL1 = Al + (size_t)(off + r1c) * KDIM + c * 8;
    }
    const __nv_bfloat16* We_h = Wh + (size_t)e * NTOT * KDIM;
    const __nv_bfloat16* We_l = Wl + (size_t)e * NTOT * KDIM;
    const __nv_bfloat16* bH0 = We_h + (size_t)(n0 + row0) * KDIM + c * 8;
    const __nv_bfloat16* bH1 = We_h + (size_t)(n0 + row1) * KDIM + c * 8;
    const __nv_bfloat16* bL0 = We_l + (size_t)(n0 + row0) * KDIM + c * 8;
    const __nv_bfloat16* bL1 = We_l + (size_t)(n0 + row1) * KDIM + c * 8;

    auto load_stage = [&](int kt, int s) {
        uint32_t tb = sb + SMEM_TILES + s * STAGE_BYTES;
        int ko = kt * 32;
        CP16(tb +         dst0, aH0 + ko);  CP16(tb +         dst1, aH1 + ko);
        CP16(tb +  8192 + dst0, aL0 + ko);  CP16(tb +  8192 + dst1, aL1 + ko);
        CP16(tb + 16384 + dst0, bH0 + ko);  CP16(tb + 16384 + dst1, bH1 + ko);
        CP16(tb + 24576 + dst0, bL0 + ko);  CP16(tb + 24576 + dst1, bL1 + ko);
        CP_COMMIT();
    };

    // ---- ldmatrix address components (fixed per thread)
    int arow = wm + (lane & 15);            // + mi*16
    int achk = lane >> 4;                   // + ks*2
    int brow = wn + ((lane >> 4) << 3) + (lane & 7);   // + np*16
    int bchk = (lane >> 3) & 1;             // + ks*2

    float acc[2][8][4] = {};

    load_stage(0, 0);
    for (int kt = 0; kt < NT; kt++) {
        int s = kt & 1;
        if (kt + 1 < NT) { load_stage(kt + 1, s ^ 1); CP_WAIT1(); }
        else             { CP_WAIT0(); }
        __syncthreads();

        uint32_t tb = sb + SMEM_TILES + s * STAGE_BYTES;
#pragma unroll
        for (int ks = 0; ks < 2; ks++) {
            uint32_t aHf[2][4], aLf[2][4];
#pragma unroll
            for (int mi = 0; mi < 2; mi++) {
                uint32_t ao = tile_off(arow + mi * 16, ks * 2 + achk);
                LDSM4(aHf[mi][0], aHf[mi][1], aHf[mi][2], aHf[mi][3], tb + ao);
                LDSM4(aLf[mi][0], aLf[mi][1], aLf[mi][2], aLf[mi][3], tb + 8192 + ao);
            }
#pragma unroll
            for (int np = 0; np < 4; np++) {
                uint32_t bo = tile_off(brow + np * 16, ks * 2 + bchk);
                uint32_t bHf[4], bLf[4];
                LDSM4(bHf[0], bHf[1], bHf[2], bHf[3], tb + 16384 + bo);
                LDSM4(bLf[0], bLf[1], bLf[2], bLf[3], tb + 24576 + bo);
#pragma unroll
                for (int mi = 0; mi < 2; mi++) {
#pragma unroll
                    for (int sub = 0; sub < 2; sub++) {
                        float* d = acc[mi][np * 2 + sub];
                        mma16816(d, aHf[mi], &bHf[sub * 2]);   // hi*hi
                        mma16816(d, aHf[mi], &bLf[sub * 2]);   // hi*lo
                        mma16816(d, aLf[mi], &bHf[sub * 2]);   // lo*hi
                    }
                }
            }
        }
        __syncthreads();
    }

    // ---- epilogue. acc[mi][nf]: {c0,c1}=row r, cols 2q,+1; {c2,c3}=row r+8
    int r = lane >> 2, q = lane & 3;
    const float* brow_bias = bias + (size_t)e * NTOT;
#pragma unroll
    for (int mi = 0; mi < 2; mi++) {
#pragma unroll
        for (int nf = 0; nf < 8; nf++) {
            float* a4 = acc[mi][nf];
            int col  = n0 + wn + nf * 8 + 2 * q;
            float bz0 = brow_bias[col], bz1 = brow_bias[col + 1];
#pragma unroll
            for (int h = 0; h < 2; h++) {
                int local = wm + mi * 16 + r + h * 8;
                if (m0 + local >= n_e) continue;
                float v0 = a4[h * 2 + 0] + bz0;
                float v1 = a4[h * 2 + 1] + bz1;
                if (IS_UP) {
                    v0 = gelu_exact(v0); v1 = gelu_exact(v1);
                    __nv_bfloat16 h0, h1, l0, l1;
                    split_bf16(v0, h0, l0); split_bf16(v1, h1, l1);
                    size_t o = (size_t)(off + m0 + local) * U_DIM + col;
                    *(__nv_bfloat162*)(g_Hh + o) = __halves2bfloat162(h0, h1);
                    *(__nv_bfloat162*)(g_Hl + o) = __halves2bfloat162(l0, l1);
                } else {
                    int   tok = s_tok[local];
                    float wgt = s_wt[local];
                    float* op = out + (size_t)tok * D_DIM + col;
                    atomicAdd(op,     wgt * v0);
                    atomicAdd(op + 1, wgt * v1);
                }
            }
        }
    }
}

// ---------------- launch -----------------------------------------------------
extern "C" void kernel_launch(void* const* d_in, const int* in_sizes, int n_in,
                              void* d_out, int out_size) {
    const float* x  = (const float*)d_in[0];
    const float* wr = (const float*)d_in[1];
    const float* wu = (const float*)d_in[2];
    const float* bu = (const float*)d_in[3];
    const float* wd = (const float*)d_in[4];
    const float* bd = (const float*)d_in[5];
    float* out = (float*)d_out;

    cudaFuncSetAttribute(moe_mma<D_DIM, true>,
                         cudaFuncAttributeMaxDynamicSharedMemorySize, SMEM_BYTES);
    cudaFuncSetAttribute(moe_mma<U_DIM, false>,
                         cudaFuncAttributeMaxDynamicSharedMemorySize, SMEM_BYTES);

    __nv_bfloat16 *xh, *xl, *wuh, *wul, *wdh, *wdl, *Hh, *Hl;
    cudaGetSymbolAddress((void**)&xh,  g_xh);
    cudaGetSymbolAddress((void**)&xl,  g_xl);
    cudaGetSymbolAddress((void**)&wuh, g_wuh);
    cudaGetSymbolAddress((void**)&wul, g_wul);
    cudaGetSymbolAddress((void**)&wdh, g_wdh);
    cudaGetSymbolAddress((void**)&wdl, g_wdl);
    cudaGetSymbolAddress((void**)&Hh,  g_Hh);
    cudaGetSymbolAddress((void**)&Hl,  g_Hl);

    cudaMemsetAsync(out, 0, (size_t)out_size * sizeof(float), 0);
    zero_cnt_kernel<<<1, 32>>>();
    router_kernel<<<T_TOK / 4, 128>>>(x, wr);
    offsets_kernel<<<1, 32>>>();

    // fp32 -> bf16 hi/lo splits
    int n_x = T_TOK * D_DIM, n_w = E_NUM * U_DIM * D_DIM;
    split_kernel<<<2048,  256>>>(x,  xh,  xl,  n_x);
    split_kernel<<<16384, 256>>>(wu, wuh, wul, n_w);
    split_kernel<<<16384, 256>>>(wd, wdh, wdl, n_w);

    // up: M=8192 routed rows, N=4096, K=1024
    moe_mma<D_DIM, true><<<dim3(U_DIM / 128, T_TOK / 128, E_NUM), 256, SMEM_BYTES>>>(
        xh, xl, wuh, wul, bu, nullptr);
    // down: M=8192 routed rows, N=1024, K=4096
    moe_mma<U_DIM, false><<<dim3(D_DIM / 128, T_TOK / 128, E_NUM), 256, SMEM_BYTES>>>(
        Hh, Hl, wdh, wdl, bd, out);
}

// round 15
// speedup vs baseline: 1.3958x; 1.3958x over previous
#include <cuda_runtime.h>
#include <cuda_fp16.h>
#include <math.h>
#include <stdint.h>

// Problem constants
#define T_TOK 4096   // B*S tokens
#define D_DIM 1024   // embed dim
#define U_DIM 4096   // ffn dim
#define E_NUM 8      // experts

// ---------------- scratch (static device globals; no allocation) -----------
__device__ __half g_xh [(size_t)T_TOK * D_DIM];
__device__ __half g_xl [(size_t)T_TOK * D_DIM];
__device__ __half g_wuh[(size_t)E_NUM * U_DIM * D_DIM];   // weights: hi only
__device__ __half g_wdh[(size_t)E_NUM * D_DIM * U_DIM];
__device__ __half g_Hh [(size_t)T_TOK * 2 * U_DIM];
__device__ __half g_Hl [(size_t)T_TOK * 2 * U_DIM];
__device__ int   g_tok[E_NUM * T_TOK];
__device__ float g_wt [E_NUM * T_TOK];
__device__ int   g_cnt[E_NUM];
__device__ int   g_off[E_NUM];

// ---------------- PTX helpers (baseline sm_80+ ISA only) -------------------
__device__ __forceinline__ uint32_t smem_u32(const void* p) {
    uint32_t a;
    asm("{ .reg .u64 t; cvta.to.shared.u64 t, %1; cvt.u32.u64 %0, t; }" : "=r"(a) : "l"(p));
    return a;
}

#define CP16(dst, src)  asm volatile("cp.async.cg.shared.global [%0], [%1], 16;" :: "r"(dst), "l"(src))
#define CP_COMMIT()     asm volatile("cp.async.commit_group;" ::: "memory")
#define CP_WAIT1()      asm volatile("cp.async.wait_group 1;" ::: "memory")
#define CP_WAIT0()      asm volatile("cp.async.wait_group 0;" ::: "memory")

#define LDSM4(r0, r1, r2, r3, addr) \
    asm volatile("ldmatrix.sync.aligned.m8n8.x4.shared.b16 {%0,%1,%2,%3}, [%4];" \
                 : "=r"(r0), "=r"(r1), "=r"(r2), "=r"(r3) : "r"(addr))

__device__ __forceinline__ void mma16816(float* d, const uint32_t* a, const uint32_t* b) {
    asm volatile(
        "mma.sync.aligned.m16n8k16.row.col.f32.f16.f16.f32 "
        "{%0,%1,%2,%3}, {%4,%5,%6,%7}, {%8,%9}, {%0,%1,%2,%3};"
        : "+f"(d[0]), "+f"(d[1]), "+f"(d[2]), "+f"(d[3])
        : "r"(a[0]), "r"(a[1]), "r"(a[2]), "r"(a[3]), "r"(b[0]), "r"(b[1]));
}

// SMEM tile: 128 rows x 4 chunks of 16B (BK=32 fp16). XOR swizzle keeps
// ldmatrix 8-row reads on distinct banks: chunk' = chunk ^ ((row>>1)&3).
__device__ __forceinline__ uint32_t tile_off(int row, int chunk) {
    return (uint32_t)(row * 64 + ((chunk ^ ((row >> 1) & 3)) << 4));
}

__device__ __forceinline__ float gelu_exact(float v) {
    return 0.5f * v * (1.f + erff(v * 0.70710678118654752f));
}
__device__ __forceinline__ void split_h(float v, __half& h, __half& l) {
    h = __float2half_rn(v);
    l = __float2half_rn(v - __half2float(h));
}

// ---------------- preprocessing: fp32 -> fp16 -------------------------------
// convert-only (weights): 8 elems/thread, 32B read / 16B write
__global__ void conv_kernel(const float* __restrict__ src,
                            __half* __restrict__ dst, int n) {
    int i = (blockIdx.x * blockDim.x + threadIdx.x) * 8;
    if (i >= n) return;
    float4 a = *(const float4*)(src + i);
    float4 b = *(const float4*)(src + i + 4);
    __half2 h[4];
    h[0] = __floats2half2_rn(a.x, a.y); h[1] = __floats2half2_rn(a.z, a.w);
    h[2] = __floats2half2_rn(b.x, b.y); h[3] = __floats2half2_rn(b.z, b.w);
    *(uint4*)(dst + i) = *(uint4*)h;
}

// split (activations): hi = fp16(v), lo = fp16(v - hi)
__global__ void split_kernel(const float* __restrict__ src,
                             __half* __restrict__ hi,
                             __half* __restrict__ lo, int n) {
    int i = (blockIdx.x * blockDim.x + threadIdx.x) * 8;
    if (i >= n) return;
    float4 a = *(const float4*)(src + i);
    float4 b = *(const float4*)(src + i + 4);
    float v[8] = {a.x, a.y, a.z, a.w, b.x, b.y, b.z, b.w};
    __half hh[8], ll[8];
#pragma unroll
    for (int j = 0; j < 8; j++) split_h(v[j], hh[j], ll[j]);
    *(uint4*)(hi + i) = *(uint4*)hh;
    *(uint4*)(lo + i) = *(uint4*)ll;
}

// ---------------- router ----------------------------------------------------
__global__ void zero_cnt_kernel() {
    if (threadIdx.x < E_NUM) g_cnt[threadIdx.x] = 0;
}

__global__ void router_kernel(const float* __restrict__ x,
                              const float* __restrict__ wr) {
    int t    = blockIdx.x * 4 + (threadIdx.x >> 5);
    int lane = threadIdx.x & 31;
    if (t >= T_TOK) return;
    const float* xr = x + (size_t)t * D_DIM;

    float logit[E_NUM];
#pragma unroll
    for (int e = 0; e < E_NUM; e++) {
        const float* w = wr + e * D_DIM;
        float s = 0.f;
        for (int i = lane; i < D_DIM; i += 32)
            s += xr[i] * w[i];
#pragma unroll
        for (int o = 16; o > 0; o >>= 1)
            s += __shfl_xor_sync(0xffffffffu, s, o);
        logit[e] = s;
    }

    if (lane == 0) {
        int e0 = 0; float l0 = logit[0];
#pragma unroll
        for (int e = 1; e < E_NUM; e++)
            if (logit[e] > l0) { l0 = logit[e]; e0 = e; }
        int e1 = -1; float l1 = -INFINITY;
#pragma unroll
        for (int e = 0; e < E_NUM; e++)
            if (e != e0 && logit[e] > l1) { l1 = logit[e]; e1 = e; }

        float p1 = expf(l1 - l0);
        float inv = 1.f / (1.f + p1);
        float w0 = inv, w1 = p1 * inv;

        int p;
        p = atomicAdd(&g_cnt[e0], 1);
        g_tok[e0 * T_TOK + p] = t;  g_wt[e0 * T_TOK + p] = w0;
        p = atomicAdd(&g_cnt[e1], 1);
        g_tok[e1 * T_TOK + p] = t;  g_wt[e1 * T_TOK + p] = w1;
    }
}

__global__ void offsets_kernel() {
    if (threadIdx.x == 0) {
        int acc = 0;
#pragma unroll
        for (int e = 0; e < E_NUM; e++) { g_off[e] = acc; acc += g_cnt[e]; }
    }
}

// ---------------- grouped GEMM: fp16 mma, 2-pass A-split -------------------
// C[m,n] = sum_k A[m,k]*B[n,k];  A = Ah + Al (exact), B = Bh (fp16).
// acc = Ah*Bh + Al*Bh = A*Bh; dropped error A*(B-Bh) ~ 2^-11 rel.
// Tile BM=128, BN=128, BK=32; 8 warps each 32(M) x 64(N).
// 3-stage cp.async pipeline, 1 sync per k-tile.
// Stage layout: [Ah 8K | Al 8K | Bh 8K] = 24KB.

static constexpr int SMEM_TILES  = 1024;
static constexpr int STAGE_BYTES = 24576;
static constexpr int SMEM_BYTES  = SMEM_TILES + 3 * STAGE_BYTES;  // 74752

template<int KDIM, bool IS_UP>
__global__ void __launch_bounds__(256, 2)
moe_mma(const __half* __restrict__ Ah, const __half* __restrict__ Al,
        const __half* __restrict__ Wh,
        const float* __restrict__ bias, float* __restrict__ out)
{
    constexpr int NTOT = IS_UP ? U_DIM : D_DIM;
    constexpr int NT   = KDIM / 32;

    int e   = blockIdx.z;
    int n_e = g_cnt[e];
    int m0  = blockIdx.y * 128;
    if (m0 >= n_e) return;
    int n0  = blockIdx.x * 128;
    int off = g_off[e];

    int tid  = threadIdx.x;
    int lane = tid & 31;
    int wid  = tid >> 5;
    int wm   = (wid & 3) * 32;   // warp M offset
    int wn   = (wid >> 2) * 64;  // warp N offset

    extern __shared__ __align__(16) char smem[];
    uint32_t sb = smem_u32(smem);
    int*   s_tok = (int*)(smem);
    float* s_wt  = (float*)(smem + 512);

    if (tid < 128) {
        int grow = m0 + tid;
        int idx  = e * T_TOK + (grow < n_e ? grow : n_e - 1);
        s_tok[tid] = g_tok[idx];
        s_wt[tid]  = g_wt[idx];
    }
    __syncthreads();

    // ---- per-thread cp.async slots: rows row0/row1, chunk c (16B)
    int c    = tid & 3;
    int row0 = tid >> 2;           // 0..63
    int row1 = row0 + 64;          // 64..127
    uint32_t dst0 = tile_off(row0, c);
    uint32_t dst1 = tile_off(row1, c);

    const __half *aH0, *aH1, *aL0, *aL1;
    if (IS_UP) {
        aH0 = Ah + (size_t)s_tok[row0] * KDIM + c * 8;
        aH1 = Ah + (size_t)s_tok[row1] * KDIM + c * 8;
        aL0 = Al + (size_t)s_tok[row0] * KDIM + c * 8;
        aL1 = Al + (size_t)s_tok[row1] * KDIM + c * 8;
    } else {
        int r0c = m0 + row0; if (r0c >= n_e) r0c = n_e - 1;
        int r1c = m0 + row1; if (r1c >= n_e) r1c = n_e - 1;
        aH0 = Ah + (size_t)(off + r0c) * KDIM + c * 8;
        aH1 = Ah + (size_t)(off + r1c) * KDIM + c * 8;
        aL0 = Al + (size_t)(off + r0c) * KDIM + c * 8;
        aL1 = Al + (size_t)(off + r1c) * KDIM + c * 8;
    }
    const __half* We = Wh + (size_t)e * NTOT * KDIM;
    const __half* bH0 = We + (size_t)(n0 + row0) * KDIM + c * 8;
    const __half* bH1 = We + (size_t)(n0 + row1) * KDIM + c * 8;

    auto load_stage = [&](int kt, int s) {
        uint32_t tb = sb + SMEM_TILES + s * STAGE_BYTES;
        int ko = kt * 32;
        CP16(tb +         dst0, aH0 + ko);  CP16(tb +         dst1, aH1 + ko);
        CP16(tb +  8192 + dst0, aL0 + ko);  CP16(tb +  8192 + dst1, aL1 + ko);
        CP16(tb + 16384 + dst0, bH0 + ko);  CP16(tb + 16384 + dst1, bH1 + ko);
        CP_COMMIT();
    };

    // ---- ldmatrix address components (fixed per thread)
    int arow = wm + (lane & 15);
    int achk = lane >> 4;
    int brow = wn + ((lane >> 4) << 3) + (lane & 7);
    int bchk = (lane >> 3) & 1;

    float acc[2][8][4] = {};

    load_stage(0, 0);
    if (NT > 1) load_stage(1, 1);
    for (int kt = 0; kt < NT; kt++) {
        if (kt + 1 < NT) CP_WAIT1();    // stage kt complete (groups in order)
        else             CP_WAIT0();
        __syncthreads();                // stage kt visible; compute(kt-1) done everywhere

        if (kt + 2 < NT) load_stage(kt + 2, (kt + 2) % 3);

        uint32_t tb = sb + SMEM_TILES + (kt % 3) * STAGE_BYTES;
#pragma unroll
        for (int ks = 0; ks < 2; ks++) {
            uint32_t aHf[2][4], aLf[2][4];
#pragma unroll
            for (int mi = 0; mi < 2; mi++) {
                uint32_t ao = tile_off(arow + mi * 16, ks * 2 + achk);
                LDSM4(aHf[mi][0], aHf[mi][1], aHf[mi][2], aHf[mi][3], tb + ao);
                LDSM4(aLf[mi][0], aLf[mi][1], aLf[mi][2], aLf[mi][3], tb + 8192 + ao);
            }
#pragma unroll
            for (int np = 0; np < 4; np++) {
                uint32_t bo = tile_off(brow + np * 16, ks * 2 + bchk);
                uint32_t bHf[4];
                LDSM4(bHf[0], bHf[1], bHf[2], bHf[3], tb + 16384 + bo);
#pragma unroll
                for (int mi = 0; mi < 2; mi++) {
#pragma unroll
                    for (int sub = 0; sub < 2; sub++) {
                        float* d = acc[mi][np * 2 + sub];
                        mma16816(d, aHf[mi], &bHf[sub * 2]);   // Ah*Bh
                        mma16816(d, aLf[mi], &bHf[sub * 2]);   // Al*Bh
                    }
                }
            }
        }
    }

    // ---- epilogue. acc[mi][nf]: {c0,c1}=row r cols 2q,2q+1; {c2,c3}=row r+8
    int r = lane >> 2, q = lane & 3;
    const float* brow_bias = bias + (size_t)e * NTOT;
#pragma unroll
    for (int mi = 0; mi < 2; mi++) {
#pragma unroll
        for (int nf = 0; nf < 8; nf++) {
            float* a4 = acc[mi][nf];
            int col  = n0 + wn + nf * 8 + 2 * q;
            float bz0 = brow_bias[col], bz1 = brow_bias[col + 1];
#pragma unroll
            for (int h = 0; h < 2; h++) {
                int local = wm + mi * 16 + r + h * 8;
                if (m0 + local >= n_e) continue;
                float v0 = a4[h * 2 + 0] + bz0;
                float v1 = a4[h * 2 + 1] + bz1;
                if (IS_UP) {
                    v0 = gelu_exact(v0); v1 = gelu_exact(v1);
                    __half h0, h1, l0, l1;
                    split_h(v0, h0, l0); split_h(v1, h1, l1);
                    size_t o = (size_t)(off + m0 + local) * U_DIM + col;
                    *(__half2*)(g_Hh + o) = __halves2half2(h0, h1);
                    *(__half2*)(g_Hl + o) = __halves2half2(l0, l1);
                } else {
                    int   tok = s_tok[local];
                    float wgt = s_wt[local];
                    float* op = out + (size_t)tok * D_DIM + col;
                    atomicAdd(op,     wgt * v0);
                    atomicAdd(op + 1, wgt * v1);
                }
            }
        }
    }
}

// ---------------- launch -----------------------------------------------------
extern "C" void kernel_launch(void* const* d_in, const int* in_sizes, int n_in,
                              void* d_out, int out_size) {
    const float* x  = (const float*)d_in[0];
    const float* wr = (const float*)d_in[1];
    const float* wu = (const float*)d_in[2];
    const float* bu = (const float*)d_in[3];
    const float* wd = (const float*)d_in[4];
    const float* bd = (const float*)d_in[5];
    float* out = (float*)d_out;

    cudaFuncSetAttribute(moe_mma<D_DIM, true>,
                         cudaFuncAttributeMaxDynamicSharedMemorySize, SMEM_BYTES);
    cudaFuncSetAttribute(moe_mma<U_DIM, false>,
                         cudaFuncAttributeMaxDynamicSharedMemorySize, SMEM_BYTES);

    __half *xh, *xl, *wuh, *wdh, *Hh, *Hl;
    cudaGetSymbolAddress((void**)&xh,  g_xh);
    cudaGetSymbolAddress((void**)&xl,  g_xl);
    cudaGetSymbolAddress((void**)&wuh, g_wuh);
    cudaGetSymbolAddress((void**)&wdh, g_wdh);
    cudaGetSymbolAddress((void**)&Hh,  g_Hh);
    cudaGetSymbolAddress((void**)&Hl,  g_Hl);

    cudaMemsetAsync(out, 0, (size_t)out_size * sizeof(float), 0);
    zero_cnt_kernel<<<1, 32>>>();
    router_kernel<<<T_TOK / 4, 128>>>(x, wr);
    offsets_kernel<<<1, 32>>>();

    int n_x = T_TOK * D_DIM;                 // 4.2M  -> 2048 blocks
    int n_w = E_NUM * U_DIM * D_DIM;         // 33.5M -> 16384 blocks
    split_kernel<<<n_x / (256 * 8), 256>>>(x, xh, xl, n_x);
    conv_kernel <<<n_w / (256 * 8), 256>>>(wu, wuh, n_w);
    conv_kernel <<<n_w / (256 * 8), 256>>>(wd, wdh, n_w);

    // up: M=8192 routed rows, N=4096, K=1024
    moe_mma<D_DIM, true><<<dim3(U_DIM / 128, T_TOK / 128, E_NUM), 256, SMEM_BYTES>>>(
        xh, xl, wuh, bu, nullptr);
    // down: M=8192 routed rows, N=1024, K=4096
    moe_mma<U_DIM, false><<<dim3(D_DIM / 128, T_TOK / 128, E_NUM), 256, SMEM_BYTES>>>(
        Hh, Hl, wdh, bd, out);
}

// round 16
// speedup vs baseline: 2.3912x; 1.7131x over previous
#include <cuda_runtime.h>
#include <cuda_fp16.h>
#include <math.h>
#include <stdint.h>

// Problem constants
#define T_TOK 4096   // B*S tokens
#define D_DIM 1024   // embed dim
#define U_DIM 4096   // ffn dim
#define E_NUM 8      // experts

// ---------------- scratch (static device globals; no allocation) -----------
__device__ __half g_xh [(size_t)T_TOK * D_DIM];
__device__ __half g_wuh[(size_t)E_NUM * U_DIM * D_DIM];
__device__ __half g_wdh[(size_t)E_NUM * D_DIM * U_DIM];
__device__ __half g_Hh [(size_t)T_TOK * 2 * U_DIM];
__device__ int   g_tok[E_NUM * T_TOK];
__device__ float g_wt [E_NUM * T_TOK];
__device__ int   g_cnt[E_NUM];
__device__ int   g_off[E_NUM];

// ---------------- PTX helpers (baseline sm_80+ ISA only) -------------------
__device__ __forceinline__ uint32_t smem_u32(const void* p) {
    uint32_t a;
    asm("{ .reg .u64 t; cvta.to.shared.u64 t, %1; cvt.u32.u64 %0, t; }" : "=r"(a) : "l"(p));
    return a;
}

#define CP16(dst, src)  asm volatile("cp.async.cg.shared.global [%0], [%1], 16;" :: "r"(dst), "l"(src))
#define CP_COMMIT()     asm volatile("cp.async.commit_group;" ::: "memory")
#define CP_WAIT1()      asm volatile("cp.async.wait_group 1;" ::: "memory")
#define CP_WAIT0()      asm volatile("cp.async.wait_group 0;" ::: "memory")

#define LDSM4(r0, r1, r2, r3, addr) \
    asm volatile("ldmatrix.sync.aligned.m8n8.x4.shared.b16 {%0,%1,%2,%3}, [%4];" \
                 : "=r"(r0), "=r"(r1), "=r"(r2), "=r"(r3) : "r"(addr))

__device__ __forceinline__ void mma16816(float* d, const uint32_t* a, const uint32_t* b) {
    asm volatile(
        "mma.sync.aligned.m16n8k16.row.col.f32.f16.f16.f32 "
        "{%0,%1,%2,%3}, {%4,%5,%6,%7}, {%8,%9}, {%0,%1,%2,%3};"
        : "+f"(d[0]), "+f"(d[1]), "+f"(d[2]), "+f"(d[3])
        : "r"(a[0]), "r"(a[1]), "r"(a[2]), "r"(a[3]), "r"(b[0]), "r"(b[1]));
}

// SMEM tile: 128 rows x 8 chunks of 16B (BK=64 fp16, 128B rows).
// XOR swizzle: chunk' = chunk ^ (row & 7) -> ldmatrix 8-row reads hit
// 8 distinct 16B bank groups; cp.async row writes cover all banks once.
__device__ __forceinline__ uint32_t tile_off(int row, int chunk) {
    return (uint32_t)(row * 128 + ((chunk ^ (row & 7)) << 4));
}

__device__ __forceinline__ float gelu_exact(float v) {
    return 0.5f * v * (1.f + erff(v * 0.70710678118654752f));
}

// ---------------- preprocessing: fp32 -> fp16 (x, w_up, w_down in one) -----
#define N_X ((int)(T_TOK * D_DIM))                 // 4,194,304
#define N_W ((int)(E_NUM * U_DIM * D_DIM))         // 33,554,432

__global__ void prep_kernel(const float* __restrict__ x,
                            const float* __restrict__ wu,
                            const float* __restrict__ wd,
                            __half* __restrict__ xh,
                            __half* __restrict__ wuh,
                            __half* __restrict__ wdh) {
    int gi = (blockIdx.x * blockDim.x + threadIdx.x) * 8;
    const float* src; __half* dst; int i;
    if (gi < N_X)            { src = x;  dst = xh;  i = gi; }
    else if (gi < N_X + N_W) { src = wu; dst = wuh; i = gi - N_X; }
    else                     { src = wd; dst = wdh; i = gi - N_X - N_W; }
    float4 a = *(const float4*)(src + i);
    float4 b = *(const float4*)(src + i + 4);
    __half2 h[4];
    h[0] = __floats2half2_rn(a.x, a.y); h[1] = __floats2half2_rn(a.z, a.w);
    h[2] = __floats2half2_rn(b.x, b.y); h[3] = __floats2half2_rn(b.z, b.w);
    *(uint4*)(dst + i) = *(uint4*)h;
}

// ---------------- router ----------------------------------------------------
__global__ void zero_cnt_kernel() {
    if (threadIdx.x < E_NUM) g_cnt[threadIdx.x] = 0;
}

__global__ void router_kernel(const float* __restrict__ x,
                              const float* __restrict__ wr) {
    int t    = blockIdx.x * 4 + (threadIdx.x >> 5);
    int lane = threadIdx.x & 31;
    if (t >= T_TOK) return;
    const float* xr = x + (size_t)t * D_DIM;

    float logit[E_NUM];
#pragma unroll
    for (int e = 0; e < E_NUM; e++) {
        const float* w = wr + e * D_DIM;
        float s = 0.f;
        for (int i = lane; i < D_DIM; i += 32)
            s += xr[i] * w[i];
#pragma unroll
        for (int o = 16; o > 0; o >>= 1)
            s += __shfl_xor_sync(0xffffffffu, s, o);
        logit[e] = s;
    }

    if (lane == 0) {
        int e0 = 0; float l0 = logit[0];
#pragma unroll
        for (int e = 1; e < E_NUM; e++)
            if (logit[e] > l0) { l0 = logit[e]; e0 = e; }
        int e1 = -1; float l1 = -INFINITY;
#pragma unroll
        for (int e = 0; e < E_NUM; e++)
            if (e != e0 && logit[e] > l1) { l1 = logit[e]; e1 = e; }

        float p1 = expf(l1 - l0);
        float inv = 1.f / (1.f + p1);
        float w0 = inv, w1 = p1 * inv;

        int p;
        p = atomicAdd(&g_cnt[e0], 1);
        g_tok[e0 * T_TOK + p] = t;  g_wt[e0 * T_TOK + p] = w0;
        p = atomicAdd(&g_cnt[e1], 1);
        g_tok[e1 * T_TOK + p] = t;  g_wt[e1 * T_TOK + p] = w1;
    }
}

__global__ void offsets_kernel() {
    if (threadIdx.x == 0) {
        int acc = 0;
#pragma unroll
        for (int e = 0; e < E_NUM; e++) { g_off[e] = acc; acc += g_cnt[e]; }
    }
}

// ---------------- grouped GEMM: fp16 mma, single pass ----------------------
// C[m,n] = sum_k A[m,k]*B[n,k], fp32 accumulators; A gathered.
// Tile BM=128, BN=128, BK=64; 8 warps each 32(M) x 64(N).
// 3-stage cp.async pipeline, 1 sync per k-tile.
// Stage layout: [A 16K | B 16K] = 32KB.

static constexpr int SMEM_TILES  = 1024;
static constexpr int STAGE_BYTES = 32768;
static constexpr int SMEM_BYTES  = SMEM_TILES + 3 * STAGE_BYTES;  // 99328

template<int KDIM, bool IS_UP>
__global__ void __launch_bounds__(256, 2)
moe_mma(const __half* __restrict__ Ah, const __half* __restrict__ Wh,
        const float* __restrict__ bias, float* __restrict__ out)
{
    constexpr int NTOT = IS_UP ? U_DIM : D_DIM;
    constexpr int NT   = KDIM / 64;

    int e   = blockIdx.z;
    int n_e = g_cnt[e];
    int m0  = blockIdx.y * 128;
    if (m0 >= n_e) return;
    int n0  = blockIdx.x * 128;
    int off = g_off[e];

    int tid  = threadIdx.x;
    int lane = tid & 31;
    int wid  = tid >> 5;
    int wm   = (wid & 3) * 32;   // warp M offset
    int wn   = (wid >> 2) * 64;  // warp N offset

    extern __shared__ __align__(16) char smem[];
    uint32_t sb = smem_u32(smem);
    int*   s_tok = (int*)(smem);
    float* s_wt  = (float*)(smem + 512);

    if (tid < 128) {
        int grow = m0 + tid;
        int idx  = e * T_TOK + (grow < n_e ? grow : n_e - 1);
        s_tok[tid] = g_tok[idx];
        s_wt[tid]  = g_wt[idx];
    }
    __syncthreads();

    // ---- per-thread cp.async slots: chunk c, rows r0+32j (j=0..3)
    int c  = tid & 7;              // 16B chunk within 128B row
    int r0 = tid >> 3;             // 0..31
    uint32_t a_dst[4], b_dst[4];
    const __half *a_src[4], *b_src[4];
    const __half* We = Wh + (size_t)e * NTOT * KDIM;
#pragma unroll
    for (int j = 0; j < 4; j++) {
        int row = r0 + 32 * j;
        a_dst[j] = tile_off(row, c);
        b_dst[j] = tile_off(row, c);
        if (IS_UP) {
            a_src[j] = Ah + (size_t)s_tok[row] * KDIM + c * 8;
        } else {
            int gr = m0 + row; if (gr >= n_e) gr = n_e - 1;
            a_src[j] = Ah + (size_t)(off + gr) * KDIM + c * 8;
        }
        b_src[j] = We + (size_t)(n0 + row) * KDIM + c * 8;
    }

    auto load_stage = [&](int kt, int s) {
        uint32_t tb = sb + SMEM_TILES + s * STAGE_BYTES;
        int ko = kt * 64;
#pragma unroll
        for (int j = 0; j < 4; j++) {
            CP16(tb +         a_dst[j], a_src[j] + ko);
            CP16(tb + 16384 + b_dst[j], b_src[j] + ko);
        }
        CP_COMMIT();
    };

    // ---- ldmatrix address components (fixed per thread)
    int arow = wm + (lane & 15);
    int achk = lane >> 4;                              // + ks*2
    int brow = wn + ((lane >> 4) << 3) + (lane & 7);
    int bchk = (lane >> 3) & 1;                        // + ks*2

    float acc[2][8][4] = {};

    load_stage(0, 0);
    if (NT > 1) load_stage(1, 1);
    for (int kt = 0; kt < NT; kt++) {
        if (kt + 1 < NT) CP_WAIT1();
        else             CP_WAIT0();
        __syncthreads();

        if (kt + 2 < NT) load_stage(kt + 2, (kt + 2) % 3);

        uint32_t tb = sb + SMEM_TILES + (kt % 3) * STAGE_BYTES;
#pragma unroll
        for (int ks = 0; ks < 4; ks++) {       // 4 x K=16 sub-tiles
            uint32_t aF[2][4];
#pragma unroll
            for (int mi = 0; mi < 2; mi++) {
                uint32_t ao = tile_off(arow + mi * 16, ks * 2 + achk);
                LDSM4(aF[mi][0], aF[mi][1], aF[mi][2], aF[mi][3], tb + ao);
            }
#pragma unroll
            for (int np = 0; np < 4; np++) {
                uint32_t bo = tile_off(brow + np * 16, ks * 2 + bchk);
                uint32_t bF[4];
                LDSM4(bF[0], bF[1], bF[2], bF[3], tb + 16384 + bo);
#pragma unroll
                for (int mi = 0; mi < 2; mi++) {
#pragma unroll
                    for (int sub = 0; sub < 2; sub++)
                        mma16816(acc[mi][np * 2 + sub], aF[mi], &bF[sub * 2]);
                }
            }
        }
    }

    // ---- epilogue. acc[mi][nf]: {c0,c1}=row r cols 2q,2q+1; {c2,c3}=row r+8
    int r = lane >> 2, q = lane & 3;
    const float* brow_bias = bias + (size_t)e * NTOT;
#pragma unroll
    for (int mi = 0; mi < 2; mi++) {
#pragma unroll
        for (int nf = 0; nf < 8; nf++) {
            float* a4 = acc[mi][nf];
            int col  = n0 + wn + nf * 8 + 2 * q;
            float bz0 = brow_bias[col], bz1 = brow_bias[col + 1];
#pragma unroll
            for (int h = 0; h < 2; h++) {
                int local = wm + mi * 16 + r + h * 8;
                if (m0 + local >= n_e) continue;
                float v0 = a4[h * 2 + 0] + bz0;
                float v1 = a4[h * 2 + 1] + bz1;
                if (IS_UP) {
                    v0 = gelu_exact(v0); v1 = gelu_exact(v1);
                    size_t o = (size_t)(off + m0 + local) * U_DIM + col;
                    *(__half2*)(g_Hh + o) = __floats2half2_rn(v0, v1);
                } else {
                    int   tok = s_tok[local];
                    float wgt = s_wt[local];
                    float* op = out + (size_t)tok * D_DIM + col;
                    atomicAdd(op,     wgt * v0);
                    atomicAdd(op + 1, wgt * v1);
                }
            }
        }
    }
}

// ---------------- launch -----------------------------------------------------
extern "C" void kernel_launch(void* const* d_in, const int* in_sizes, int n_in,
                              void* d_out, int out_size) {
    const float* x  = (const float*)d_in[0];
    const float* wr = (const float*)d_in[1];
    const float* wu = (const float*)d_in[2];
    const float* bu = (const float*)d_in[3];
    const float* wd = (const float*)d_in[4];
    const float* bd = (const float*)d_in[5];
    float* out = (float*)d_out;

    cudaFuncSetAttribute(moe_mma<D_DIM, true>,
                         cudaFuncAttributeMaxDynamicSharedMemorySize, SMEM_BYTES);
    cudaFuncSetAttribute(moe_mma<U_DIM, false>,
                         cudaFuncAttributeMaxDynamicSharedMemorySize, SMEM_BYTES);

    __half *xh, *wuh, *wdh, *Hh;
    cudaGetSymbolAddress((void**)&xh,  g_xh);
    cudaGetSymbolAddress((void**)&wuh, g_wuh);
    cudaGetSymbolAddress((void**)&wdh, g_wdh);
    cudaGetSymbolAddress((void**)&Hh,  g_Hh);

    // Order keeps the up-GEMM at kernel slot 5 for the ncu -s5 -c1 window.
    zero_cnt_kernel<<<1, 32>>>();
    router_kernel<<<T_TOK / 4, 128>>>(x, wr);
    offsets_kernel<<<1, 32>>>();

    int total = N_X + 2 * N_W;                     // 71,303,168 (8 | total)
    prep_kernel<<<total / (256 * 8), 256>>>(x, wu, wd, xh, wuh, wdh);

    // up: M=8192 routed rows, N=4096, K=1024
    moe_mma<D_DIM, true><<<dim3(U_DIM / 128, T_TOK / 128, E_NUM), 256, SMEM_BYTES>>>(
        xh, wuh, bu, nullptr);

    cudaMemsetAsync(out, 0, (size_t)out_size * sizeof(float), 0);

    // down: M=8192 routed rows, N=1024, K=4096
    moe_mma<U_DIM, false><<<dim3(D_DIM / 128, T_TOK / 128, E_NUM), 256, SMEM_BYTES>>>(
        Hh, wdh, bd, out);
}